// round 5
// baseline (speedup 1.0000x reference)
#include <cuda_runtime.h>
#include <math.h>

#define L_ 4
#define H_ 12
#define E_ 768
#define T_ 1024
#define B_ 4
#define V_ 50257
#define D_ 64
#define M_ (B_*T_)     // 4096
#define E3_ (3*E_)     // 2304
#define E4_ (4*E_)     // 3072

// ---------------- scratch (static device globals; no allocation) ----------
__device__ float g_x  [(size_t)M_*E_];
__device__ float g_h  [(size_t)M_*E_];
__device__ float g_qkv[(size_t)M_*E3_];
__device__ float g_y  [(size_t)M_*E_];
__device__ float g_fc [(size_t)M_*E4_];
__device__ float g_logp[B_*(T_-1)];
// tf32-rounded weight copies (converted once per launch)
__device__ float g_w_attn[(size_t)L_*E3_*E_];
__device__ float g_w_proj[(size_t)L_*E_*E_];
__device__ float g_w_fc  [(size_t)L_*E4_*E_];
__device__ float g_w_out [(size_t)L_*E_*E4_];
__device__ float g_w_wte [(size_t)V_*E_];

// ---------------- reductions ----------------------------------------------
__device__ __forceinline__ float blockReduceSum(float v, float* red) {
    int lane = threadIdx.x & 31, wid = threadIdx.x >> 5;
    #pragma unroll
    for (int o = 16; o; o >>= 1) v += __shfl_down_sync(0xffffffffu, v, o);
    __syncthreads();
    if (lane == 0) red[wid] = v;
    __syncthreads();
    if (threadIdx.x == 0) {
        float s = 0.f;
        int nw = (blockDim.x + 31) >> 5;
        for (int i = 0; i < nw; i++) s += red[i];
        red[0] = s;
    }
    __syncthreads();
    return red[0];
}

// ---------------- tf32 helpers ---------------------------------------------
__device__ __forceinline__ float to_tf32(float f) {
    unsigned r;
    asm("cvt.rna.tf32.f32 %0, %1;" : "=r"(r) : "f"(f));
    return __uint_as_float(r);
}

__device__ __forceinline__ void split_tf32(float x, unsigned& hi, unsigned& lo) {
    float h = to_tf32(x);
    hi = __float_as_uint(h);
    lo = __float_as_uint(to_tf32(x - h));
}

#define MMA_TF32(acc, a0,a1,a2,a3, b0,b1)                                   \
    asm volatile(                                                            \
        "mma.sync.aligned.m16n8k8.row.col.f32.tf32.tf32.f32 "               \
        "{%0,%1,%2,%3}, {%4,%5,%6,%7}, {%8,%9}, {%0,%1,%2,%3};"             \
        : "+f"((acc)[0]), "+f"((acc)[1]), "+f"((acc)[2]), "+f"((acc)[3])    \
        : "r"(a0), "r"(a1), "r"(a2), "r"(a3), "r"(b0), "r"(b1))

// ---------------- weight tf32 pre-rounding ---------------------------------
__global__ void cvt_tf32_kernel(const float4* __restrict__ in,
                                float4* __restrict__ out, int n4) {
    int i = blockIdx.x * 256 + threadIdx.x;
    if (i < n4) {
        float4 v = in[i];
        v.x = to_tf32(v.x); v.y = to_tf32(v.y);
        v.z = to_tf32(v.z); v.w = to_tf32(v.w);
        out[i] = v;
    }
}

// ---------------- embedding -----------------------------------------------
__global__ void embed_kernel(const int* __restrict__ idx,
                             const float* __restrict__ wte,
                             const float* __restrict__ wpe) {
    int i = blockIdx.x * 256 + threadIdx.x;
    int bt = i / E_, e = i - bt * E_;
    int t = bt & (T_ - 1);
    g_x[i] = wte[(size_t)idx[bt] * E_ + e] + wpe[(size_t)t * E_ + e];
}

// ---------------- layernorm (output pre-rounded to tf32) -------------------
__global__ void ln_kernel(const float* __restrict__ in,
                          const float* __restrict__ w,
                          const float* __restrict__ b,
                          float* __restrict__ out) {
    int row = blockIdx.x;
    const float* x = in + (size_t)row * E_;
    __shared__ float sdata[E_];
    __shared__ float red[32];
    __shared__ float s_mean, s_rstd;
    float local = 0.f;
    for (int i = threadIdx.x; i < E_; i += 256) { float v = x[i]; sdata[i] = v; local += v; }
    float tot = blockReduceSum(local, red);
    if (threadIdx.x == 0) s_mean = tot * (1.0f / E_);
    __syncthreads();
    float m = s_mean, lv = 0.f;
    for (int i = threadIdx.x; i < E_; i += 256) { float d = sdata[i] - m; lv += d * d; }
    float var = blockReduceSum(lv, red);
    if (threadIdx.x == 0) s_rstd = rsqrtf(var * (1.0f / E_) + 1e-5f);
    __syncthreads();
    float r = s_rstd;
    float* o = out + (size_t)row * E_;
    for (int i = threadIdx.x; i < E_; i += 256)
        o[i] = to_tf32((sdata[i] - m) * r * w[i] + b[i]);
}

// ---------------- TF32 GEMM: C = A[MxK] * B[NxK]^T --------------------------
// A and B already tf32-rounded; no cvt in the inner loop.
// 128x128x16 tile, 256 threads (2m x 4n warps, 64x32 warp tile),
// 4-stage cp.async pipeline, m-major smem with chunk-XOR swizzle.
#define STAGES 4
#define GEMM_SMEM (STAGES * 128 * 16 * 4 * 2)

__global__ __launch_bounds__(256, 2)
void gemm_tf32(const float* __restrict__ A, const float* __restrict__ B,
               const float* __restrict__ bias, const float* __restrict__ res,
               float* __restrict__ C, int M, int N, int K, int gelu) {
    extern __shared__ float smem[];
    float* As = smem;                       // [STAGES][128*16]
    float* Bs = smem + STAGES * 2048;

    int nbn = (N + 127) >> 7;
    int bid = blockIdx.x;
    int bpg = 8 * nbn;                      // 8 m-rows per L2 group
    int grp = bid / bpg, rr0 = bid % bpg;
    int m0 = (grp * 8 + (rr0 & 7)) << 7;
    int n0 = (rr0 >> 3) << 7;

    int tid = threadIdx.x;
    int lane = tid & 31, wid = tid >> 5;
    int wm = wid >> 2, wn = wid & 3;        // 2 x 4 warps
    int la = lane & 3, lg = lane >> 2;
    int sw = (lg >> 1) & 3;                 // frag-load swizzle constant

    int gch = 2 * tid;
    int lm = gch >> 2, lc = gch & 3;
    int lsw = (lm >> 1) & 3;
    int soff0 = lm * 16 + ((lc ^ lsw) << 2);
    int soff1 = lm * 16 + (((lc + 1) ^ lsw) << 2);
    const float* gA = A + (size_t)(m0 + lm) * K + lc * 4;
    int bn = n0 + lm;
    int bok = (bn < N) ? 16 : 0;
    const float* gB = B + (size_t)(bok ? bn : 0) * K + lc * 4;
    unsigned sAb = (unsigned)__cvta_generic_to_shared(As);
    unsigned sBb = (unsigned)__cvta_generic_to_shared(Bs);

    auto issue = [&](int stage, int kb) {
        unsigned d0 = sAb + (unsigned)(stage * 2048 + soff0) * 4u;
        unsigned d1 = sAb + (unsigned)(stage * 2048 + soff1) * 4u;
        unsigned e0 = sBb + (unsigned)(stage * 2048 + soff0) * 4u;
        unsigned e1 = sBb + (unsigned)(stage * 2048 + soff1) * 4u;
        const float* pa = gA + kb;
        const float* pb = gB + kb;
        asm volatile("cp.async.cg.shared.global [%0], [%1], 16;" :: "r"(d0), "l"(pa));
        asm volatile("cp.async.cg.shared.global [%0], [%1], 16;" :: "r"(d1), "l"(pa + 4));
        asm volatile("cp.async.cg.shared.global [%0], [%1], 16, %2;" :: "r"(e0), "l"(pb), "r"(bok));
        asm volatile("cp.async.cg.shared.global [%0], [%1], 16, %2;" :: "r"(e1), "l"(pb + 4), "r"(bok));
    };

    float acc[4][4][4];
    #pragma unroll
    for (int i = 0; i < 4; i++)
        #pragma unroll
        for (int j = 0; j < 4; j++)
            #pragma unroll
            for (int k = 0; k < 4; k++) acc[i][j][k] = 0.f;

    int nk = K >> 4;
    issue(0, 0);  asm volatile("cp.async.commit_group;");
    issue(1, 16); asm volatile("cp.async.commit_group;");
    issue(2, 32); asm volatile("cp.async.commit_group;");

    for (int kt = 0; kt < nk; kt++) {
        asm volatile("cp.async.wait_group %0;" :: "n"(STAGES - 2));
        __syncthreads();
        int pf = kt + STAGES - 1;
        if (pf < nk) issue(pf & (STAGES - 1), pf << 4);
        asm volatile("cp.async.commit_group;");

        const float* as = As + (kt & (STAGES - 1)) * 2048;
        const float* bs = Bs + (kt & (STAGES - 1)) * 2048;

        #pragma unroll
        for (int ks = 0; ks < 16; ks += 8) {
            int c0 = ks >> 2;
            int colA = ((c0 ^ sw) << 2) + la;          // k = ks+la
            int colB = (((c0 + 1) ^ sw) << 2) + la;    // k = ks+la+4
            unsigned af[4][4], bf[4][2];
            #pragma unroll
            for (int mt = 0; mt < 4; mt++) {
                int mb = (wm * 64 + mt * 16 + lg) * 16;
                af[mt][0] = __float_as_uint(as[mb + colA]);
                af[mt][1] = __float_as_uint(as[mb + 128 + colA]);
                af[mt][2] = __float_as_uint(as[mb + colB]);
                af[mt][3] = __float_as_uint(as[mb + 128 + colB]);
            }
            #pragma unroll
            for (int nt = 0; nt < 4; nt++) {
                int nb = (wn * 32 + nt * 8 + lg) * 16;
                bf[nt][0] = __float_as_uint(bs[nb + colA]);
                bf[nt][1] = __float_as_uint(bs[nb + colB]);
            }
            #pragma unroll
            for (int mt = 0; mt < 4; mt++)
                #pragma unroll
                for (int nt = 0; nt < 4; nt++)
                    MMA_TF32(acc[mt][nt], af[mt][0], af[mt][1], af[mt][2], af[mt][3],
                             bf[nt][0], bf[nt][1]);
        }
    }

    // epilogue
    #pragma unroll
    for (int mt = 0; mt < 4; mt++) {
        int rbase = m0 + wm * 64 + mt * 16 + lg;
        #pragma unroll
        for (int nt = 0; nt < 4; nt++) {
            int cbase = n0 + wn * 32 + nt * 8 + la * 2;
            #pragma unroll
            for (int half = 0; half < 2; half++) {
                int rw = rbase + half * 8;
                #pragma unroll
                for (int cc = 0; cc < 2; cc++) {
                    int c = cbase + cc;
                    if (c < N) {
                        float v = acc[mt][nt][half * 2 + cc];
                        if (bias) v += bias[c];
                        if (gelu) {
                            float t = v;
                            v = to_tf32(0.5f * t * (1.0f + tanhf(0.7978845608028654f *
                                    (t + 0.044715f * t * t * t))));
                        }
                        size_t off = (size_t)rw * N + c;
                        if (res) v += res[off];
                        C[off] = v;
                    }
                }
            }
        }
    }
}

// ---------------- fused flash attention (3xTF32 mma, online softmax) -------
// 128 q-rows per block, 8 warps (16 q-rows per warp), k-tiles of 64.
#define FQ 128
#define FATT_SMEM (((FQ + 64 + 64 + FQ) * 68 + 3 * FQ) * 4)

__global__ __launch_bounds__(256)
void flash_attn(const float* __restrict__ qkv, float* __restrict__ y) {
    extern __shared__ float fsm[];
    float (*Qs)[68] = (float(*)[68])(fsm);
    float (*Ks)[68] = (float(*)[68])(fsm + FQ * 68);
    float (*Vs)[68] = (float(*)[68])(fsm + (FQ + 64) * 68);
    float (*Ps)[68] = (float(*)[68])(fsm + (FQ + 128) * 68);
    float* m_s = fsm + (2 * FQ + 128) * 68;
    float* l_s = m_s + FQ;
    float* alpha_s = l_s + FQ;

    int bh = blockIdx.y;
    int b = bh / H_, h = bh % H_;
    int q0 = blockIdx.x * FQ;
    int tid = threadIdx.x;
    int lane = tid & 31, wm = tid >> 5;     // 8 warps x 16 q rows
    int la = lane & 3, lg = lane >> 2;

    // load Q tile [128 q][64 d]
    #pragma unroll
    for (int i = 0; i < 8; i++) {
        int f4 = tid + i * 256;
        int row = f4 >> 4, c = (f4 & 15) << 2;
        *(float4*)&Qs[row][c] =
            *(const float4*)(qkv + (size_t)(b * T_ + q0 + row) * E3_ + h * D_ + c);
    }
    if (tid < FQ) { m_s[tid] = -1e30f; l_s[tid] = 0.f; }

    float acc_o[8][4];
    #pragma unroll
    for (int i = 0; i < 8; i++)
        #pragma unroll
        for (int j = 0; j < 4; j++) acc_o[i][j] = 0.f;

    int row0 = wm * 16 + lg;
    int row1 = row0 + 8;

    int ktiles = (q0 >> 6) + 2;
    for (int kt = 0; kt < ktiles; kt++) {
        int k0 = kt << 6;
        __syncthreads();
        #pragma unroll
        for (int i = 0; i < 4; i++) {
            int f4 = tid + i * 256;
            int row = f4 >> 4, c = (f4 & 15) << 2;
            const float* base = qkv + (size_t)(b * T_ + k0 + row) * E3_ + h * D_ + c;
            *(float4*)&Ks[row][c] = *(const float4*)(base + E_);
            *(float4*)&Vs[row][c] = *(const float4*)(base + 2 * E_);
        }
        __syncthreads();

        float acc_s[8][4];
        #pragma unroll
        for (int i = 0; i < 8; i++)
            #pragma unroll
            for (int j = 0; j < 4; j++) acc_s[i][j] = 0.f;

        #pragma unroll
        for (int ks = 0; ks < 64; ks += 8) {
            unsigned ah[4], al[4];
            split_tf32(Qs[row0][ks + la    ], ah[0], al[0]);
            split_tf32(Qs[row1][ks + la    ], ah[1], al[1]);
            split_tf32(Qs[row0][ks + la + 4], ah[2], al[2]);
            split_tf32(Qs[row1][ks + la + 4], ah[3], al[3]);
            #pragma unroll
            for (int nt = 0; nt < 8; nt++) {
                int cb = nt * 8;
                unsigned bh0, bl0, bh1, bl1;
                split_tf32(Ks[cb + lg][ks + la    ], bh0, bl0);
                split_tf32(Ks[cb + lg][ks + la + 4], bh1, bl1);
                MMA_TF32(acc_s[nt], al[0], al[1], al[2], al[3], bh0, bh1);
                MMA_TF32(acc_s[nt], ah[0], ah[1], ah[2], ah[3], bl0, bl1);
                MMA_TF32(acc_s[nt], ah[0], ah[1], ah[2], ah[3], bh0, bh1);
            }
        }
        #pragma unroll
        for (int nt = 0; nt < 8; nt++) {
            int cb = nt * 8 + 2 * la;
            #pragma unroll
            for (int rr = 0; rr < 2; rr++) {
                int rloc = rr ? row1 : row0;
                int grow = q0 + rloc;
                #pragma unroll
                for (int cc = 0; cc < 2; cc++) {
                    int gcol = k0 + cb + cc;
                    float v = acc_s[nt][rr * 2 + cc] * 0.125f;
                    if (gcol > grow) v = -1e30f;
                    Ps[rloc][cb + cc] = v;
                }
            }
        }
        __syncthreads();

        {
            int r = tid >> 1, half = tid & 1;
            int c0 = half * 32;
            float mx = -1e30f;
            #pragma unroll 8
            for (int c = 0; c < 32; c++) mx = fmaxf(mx, Ps[r][c0 + c]);
            mx = fmaxf(mx, __shfl_xor_sync(0xffffffffu, mx, 1));
            float m_new = fmaxf(m_s[r], mx);
            float s = 0.f;
            #pragma unroll 8
            for (int c = 0; c < 32; c++) {
                float p = __expf(Ps[r][c0 + c] - m_new);
                Ps[r][c0 + c] = p;
                s += p;
            }
            s += __shfl_xor_sync(0xffffffffu, s, 1);
            if (half == 0) {
                float alpha = __expf(m_s[r] - m_new);
                l_s[r] = l_s[r] * alpha + s;
                m_s[r] = m_new;
                alpha_s[r] = alpha;
            }
        }
        __syncthreads();

        {
            float a0 = alpha_s[row0], a1 = alpha_s[row1];
            #pragma unroll
            for (int nt = 0; nt < 8; nt++) {
                acc_o[nt][0] *= a0; acc_o[nt][1] *= a0;
                acc_o[nt][2] *= a1; acc_o[nt][3] *= a1;
            }
        }
        #pragma unroll
        for (int ks = 0; ks < 64; ks += 8) {
            unsigned ah[4], al[4];
            split_tf32(Ps[row0][ks + la    ], ah[0], al[0]);
            split_tf32(Ps[row1][ks + la    ], ah[1], al[1]);
            split_tf32(Ps[row0][ks + la + 4], ah[2], al[2]);
            split_tf32(Ps[row1][ks + la + 4], ah[3], al[3]);
            #pragma unroll
            for (int nt = 0; nt < 8; nt++) {
                int cb = nt * 8;
                unsigned bh0, bl0, bh1, bl1;
                split_tf32(Vs[ks + la    ][cb + lg], bh0, bl0);
                split_tf32(Vs[ks + la + 4][cb + lg], bh1, bl1);
                MMA_TF32(acc_o[nt], al[0], al[1], al[2], al[3], bh0, bh1);
                MMA_TF32(acc_o[nt], ah[0], ah[1], ah[2], ah[3], bl0, bl1);
                MMA_TF32(acc_o[nt], ah[0], ah[1], ah[2], ah[3], bh0, bh1);
            }
        }
    }

    // epilogue: normalize, round to tf32 (y is only ever a GEMM-A operand)
    float inv0 = 1.0f / l_s[row0];
    float inv1 = 1.0f / l_s[row1];
    size_t yb0 = (size_t)(b * T_ + q0 + row0) * E_ + h * D_;
    size_t yb1 = (size_t)(b * T_ + q0 + row1) * E_ + h * D_;
    #pragma unroll
    for (int nt = 0; nt < 8; nt++) {
        int cb = nt * 8 + 2 * la;
        y[yb0 + cb    ] = to_tf32(acc_o[nt][0] * inv0);
        y[yb0 + cb + 1] = to_tf32(acc_o[nt][1] * inv0);
        y[yb1 + cb    ] = to_tf32(acc_o[nt][2] * inv1);
        y[yb1 + cb + 1] = to_tf32(acc_o[nt][3] * inv1);
    }
}

// ---------------- loss (single-pass online softmax) ------------------------
__global__ void loss_rows(const float* __restrict__ logits,
                          const int* __restrict__ targets) {
    int r = blockIdx.x;
    int b = r / (T_ - 1), t = r % (T_ - 1);
    const float* row = logits + (size_t)(b * T_ + t) * V_;
    int label = targets[b * T_ + t + 1];
    float mx = -1e30f, s = 0.f;
    for (int i = threadIdx.x; i < V_; i += 256) {
        float v = row[i];
        float mN = fmaxf(mx, v);
        s = s * __expf(mx - mN) + __expf(v - mN);
        mx = mN;
    }
    #pragma unroll
    for (int o = 16; o; o >>= 1) {
        float m2 = __shfl_down_sync(0xffffffffu, mx, o);
        float s2 = __shfl_down_sync(0xffffffffu, s, o);
        float mN = fmaxf(mx, m2);
        s = s * __expf(mx - mN) + s2 * __expf(m2 - mN);
        mx = mN;
    }
    __shared__ float smx[8], ssm[8];
    int lane = threadIdx.x & 31, wid = threadIdx.x >> 5;
    if (lane == 0) { smx[wid] = mx; ssm[wid] = s; }
    __syncthreads();
    if (threadIdx.x == 0) {
        float Mv = smx[0], Sv = ssm[0];
        #pragma unroll
        for (int i = 1; i < 8; i++) {
            float mN = fmaxf(Mv, smx[i]);
            Sv = Sv * __expf(Mv - mN) + ssm[i] * __expf(smx[i] - mN);
            Mv = mN;
        }
        g_logp[r] = row[label] - Mv - logf(Sv);
    }
}

__global__ void loss_final(float* __restrict__ out, long long pos) {
    __shared__ float red[32];
    float s = 0.f;
    for (int i = threadIdx.x; i < B_ * (T_ - 1); i += 256) s += g_logp[i];
    s = blockReduceSum(s, red);
    if (threadIdx.x == 0) out[pos] = -s / (float)(B_ * (T_ - 1));
}

// ---------------- driver ----------------------------------------------------
static inline int gemm_grid(int M, int N) {
    return (M >> 7) * ((N + 127) >> 7);
}

static inline void cvt_weights(const float* src, float* dst, long long n) {
    int n4 = (int)(n >> 2);
    cvt_tf32_kernel<<<(n4 + 255) / 256, 256>>>(
        (const float4*)src, (float4*)dst, n4);
}

extern "C" void kernel_launch(void* const* d_in, const int* in_sizes, int n_in,
                              void* d_out, int out_size) {
    const int*   idx     = (const int*)  d_in[0];
    const int*   targets = (const int*)  d_in[1];
    const float* wte     = (const float*)d_in[2];
    const float* wpe     = (const float*)d_in[3];
    const float* ln1_w   = (const float*)d_in[4];
    const float* ln1_b   = (const float*)d_in[5];
    const float* attn_w  = (const float*)d_in[6];
    const float* attn_b  = (const float*)d_in[7];
    const float* proj_w  = (const float*)d_in[8];
    const float* proj_b  = (const float*)d_in[9];
    const float* ln2_w   = (const float*)d_in[10];
    const float* ln2_b   = (const float*)d_in[11];
    const float* fc_w    = (const float*)d_in[12];
    const float* fc_b    = (const float*)d_in[13];
    const float* out_w   = (const float*)d_in[14];
    const float* out_b   = (const float*)d_in[15];
    const float* lnf_w   = (const float*)d_in[16];
    const float* lnf_b   = (const float*)d_in[17];
    float* out = (float*)d_out;

    float *x, *h, *qkv, *y, *fc;
    float *w_attn, *w_proj, *w_fc, *w_out, *w_wte;
    cudaGetSymbolAddress((void**)&x,   g_x);
    cudaGetSymbolAddress((void**)&h,   g_h);
    cudaGetSymbolAddress((void**)&qkv, g_qkv);
    cudaGetSymbolAddress((void**)&y,   g_y);
    cudaGetSymbolAddress((void**)&fc,  g_fc);
    cudaGetSymbolAddress((void**)&w_attn, g_w_attn);
    cudaGetSymbolAddress((void**)&w_proj, g_w_proj);
    cudaGetSymbolAddress((void**)&w_fc,   g_w_fc);
    cudaGetSymbolAddress((void**)&w_out,  g_w_out);
    cudaGetSymbolAddress((void**)&w_wte,  g_w_wte);

    cudaFuncSetAttribute(flash_attn,
                         cudaFuncAttributeMaxDynamicSharedMemorySize, FATT_SMEM);
    cudaFuncSetAttribute(gemm_tf32,
                         cudaFuncAttributeMaxDynamicSharedMemorySize, GEMM_SMEM);

    // pre-round all GEMM-B operands to tf32 (once per launch)
    cvt_weights(attn_w, w_attn, (long long)L_ * E3_ * E_);
    cvt_weights(proj_w, w_proj, (long long)L_ * E_ * E_);
    cvt_weights(fc_w,   w_fc,   (long long)L_ * E4_ * E_);
    cvt_weights(out_w,  w_out,  (long long)L_ * E_ * E4_);
    cvt_weights(wte,    w_wte,  (long long)V_ * E_);

    embed_kernel<<<(M_ * E_) / 256, 256>>>(idx, wte, wpe);

    for (int l = 0; l < L_; l++) {
        ln_kernel<<<M_, 256>>>(x, ln1_w + (size_t)l * E_, ln1_b + (size_t)l * E_, h);
        gemm_tf32<<<gemm_grid(M_, E3_), 256, GEMM_SMEM>>>(
            h, w_attn + (size_t)l * E3_ * E_, attn_b + (size_t)l * E3_,
            nullptr, qkv, M_, E3_, E_, 0);
        flash_attn<<<dim3(T_ / FQ, B_ * H_), 256, FATT_SMEM>>>(qkv, y);
        gemm_tf32<<<gemm_grid(M_, E_), 256, GEMM_SMEM>>>(
            y, w_proj + (size_t)l * E_ * E_, proj_b + (size_t)l * E_,
            x, x, M_, E_, E_, 0);
        ln_kernel<<<M_, 256>>>(x, ln2_w + (size_t)l * E_, ln2_b + (size_t)l * E_, h);
        gemm_tf32<<<gemm_grid(M_, E4_), 256, GEMM_SMEM>>>(
            h, w_fc + (size_t)l * E4_ * E_, fc_b + (size_t)l * E4_,
            nullptr, fc, M_, E4_, E_, 1);
        gemm_tf32<<<gemm_grid(M_, E_), 256, GEMM_SMEM>>>(
            fc, w_out + (size_t)l * E_ * E4_, out_b + (size_t)l * E_,
            x, x, M_, E_, E4_, 0);
    }

    ln_kernel<<<M_, 256>>>(x, lnf_w, lnf_b, h);
    gemm_tf32<<<gemm_grid(M_, V_), 256, GEMM_SMEM>>>(
        h, w_wte, nullptr, nullptr, out, M_, V_, E_, 0);

    loss_rows<<<B_ * (T_ - 1), 256>>>(out, targets);
    long long pos = (long long)M_ * V_;
    if (pos < (long long)out_size)
        loss_final<<<1, 256>>>(out, pos);
}

// round 6
// speedup vs baseline: 1.1557x; 1.1557x over previous
#include <cuda_runtime.h>
#include <math.h>

#define L_ 4
#define H_ 12
#define E_ 768
#define T_ 1024
#define B_ 4
#define V_ 50257
#define D_ 64
#define M_ (B_*T_)     // 4096
#define E3_ (3*E_)     // 2304
#define E4_ (4*E_)     // 3072

// ---------------- scratch (static device globals; no allocation) ----------
__device__ float g_x  [(size_t)M_*E_];
__device__ float g_h  [(size_t)M_*E_];
__device__ float g_qkv[(size_t)M_*E3_];
__device__ float g_y  [(size_t)M_*E_];
__device__ float g_fc [(size_t)M_*E4_];
__device__ float g_logp[B_*(T_-1)];
// tf32-rounded weight copies (converted once per launch)
__device__ float g_w_attn[(size_t)L_*E3_*E_];
__device__ float g_w_proj[(size_t)L_*E_*E_];
__device__ float g_w_fc  [(size_t)L_*E4_*E_];
__device__ float g_w_out [(size_t)L_*E_*E4_];
__device__ float g_w_wte [(size_t)V_*E_];

// ---------------- reductions ----------------------------------------------
__device__ __forceinline__ float blockReduceSum(float v, float* red) {
    int lane = threadIdx.x & 31, wid = threadIdx.x >> 5;
    #pragma unroll
    for (int o = 16; o; o >>= 1) v += __shfl_down_sync(0xffffffffu, v, o);
    __syncthreads();
    if (lane == 0) red[wid] = v;
    __syncthreads();
    if (threadIdx.x == 0) {
        float s = 0.f;
        int nw = (blockDim.x + 31) >> 5;
        for (int i = 0; i < nw; i++) s += red[i];
        red[0] = s;
    }
    __syncthreads();
    return red[0];
}

// ---------------- tf32 helpers ---------------------------------------------
__device__ __forceinline__ float to_tf32(float f) {
    unsigned r;
    asm("cvt.rna.tf32.f32 %0, %1;" : "=r"(r) : "f"(f));
    return __uint_as_float(r);
}

__device__ __forceinline__ void split_tf32(float x, unsigned& hi, unsigned& lo) {
    float h = to_tf32(x);
    hi = __float_as_uint(h);
    lo = __float_as_uint(to_tf32(x - h));
}

#define MMA_TF32(acc, a0,a1,a2,a3, b0,b1)                                   \
    asm volatile(                                                            \
        "mma.sync.aligned.m16n8k8.row.col.f32.tf32.tf32.f32 "               \
        "{%0,%1,%2,%3}, {%4,%5,%6,%7}, {%8,%9}, {%0,%1,%2,%3};"             \
        : "+f"((acc)[0]), "+f"((acc)[1]), "+f"((acc)[2]), "+f"((acc)[3])    \
        : "r"(a0), "r"(a1), "r"(a2), "r"(a3), "r"(b0), "r"(b1))

#define LDSM_X4(r0,r1,r2,r3, addr)                                          \
    asm volatile(                                                            \
        "ldmatrix.sync.aligned.m8n8.x4.shared.b16 {%0,%1,%2,%3}, [%4];"     \
        : "=r"(r0), "=r"(r1), "=r"(r2), "=r"(r3) : "r"(addr))

// ---------------- weight tf32 pre-rounding ---------------------------------
__global__ void cvt_tf32_kernel(const float4* __restrict__ in,
                                float4* __restrict__ out, int n4) {
    int i = blockIdx.x * 256 + threadIdx.x;
    if (i < n4) {
        float4 v = in[i];
        v.x = to_tf32(v.x); v.y = to_tf32(v.y);
        v.z = to_tf32(v.z); v.w = to_tf32(v.w);
        out[i] = v;
    }
}

// ---------------- embedding -----------------------------------------------
__global__ void embed_kernel(const int* __restrict__ idx,
                             const float* __restrict__ wte,
                             const float* __restrict__ wpe) {
    int i = blockIdx.x * 256 + threadIdx.x;
    int bt = i / E_, e = i - bt * E_;
    int t = bt & (T_ - 1);
    g_x[i] = wte[(size_t)idx[bt] * E_ + e] + wpe[(size_t)t * E_ + e];
}

// ---------------- layernorm (output pre-rounded to tf32) -------------------
__global__ void ln_kernel(const float* __restrict__ in,
                          const float* __restrict__ w,
                          const float* __restrict__ b,
                          float* __restrict__ out) {
    int row = blockIdx.x;
    const float* x = in + (size_t)row * E_;
    __shared__ float sdata[E_];
    __shared__ float red[32];
    __shared__ float s_mean, s_rstd;
    float local = 0.f;
    for (int i = threadIdx.x; i < E_; i += 256) { float v = x[i]; sdata[i] = v; local += v; }
    float tot = blockReduceSum(local, red);
    if (threadIdx.x == 0) s_mean = tot * (1.0f / E_);
    __syncthreads();
    float m = s_mean, lv = 0.f;
    for (int i = threadIdx.x; i < E_; i += 256) { float d = sdata[i] - m; lv += d * d; }
    float var = blockReduceSum(lv, red);
    if (threadIdx.x == 0) s_rstd = rsqrtf(var * (1.0f / E_) + 1e-5f);
    __syncthreads();
    float r = s_rstd;
    float* o = out + (size_t)row * E_;
    for (int i = threadIdx.x; i < E_; i += 256)
        o[i] = to_tf32((sdata[i] - m) * r * w[i] + b[i]);
}

// ---------------- TF32 GEMM: C = A[MxK] * B[NxK]^T --------------------------
// A and B already tf32-rounded. Fragments via ldmatrix.x4 (b16 view of fp32).
// 128x128x16 tile, 256 threads (2m x 4n warps, 64x32 warp tile),
// 4-stage cp.async pipeline, m-major smem with chunk-XOR swizzle.
#define STAGES 4
#define GEMM_SMEM (STAGES * 128 * 16 * 4 * 2)

__global__ __launch_bounds__(256, 2)
void gemm_tf32(const float* __restrict__ A, const float* __restrict__ B,
               const float* __restrict__ bias, const float* __restrict__ res,
               float* __restrict__ C, int M, int N, int K, int gelu) {
    extern __shared__ float smem[];
    float* As = smem;                       // [STAGES][128*16]
    float* Bs = smem + STAGES * 2048;

    int nbn = (N + 127) >> 7;
    int bid = blockIdx.x;
    int bpg = 8 * nbn;                      // 8 m-rows per L2 group
    int grp = bid / bpg, rr0 = bid % bpg;
    int m0 = (grp * 8 + (rr0 & 7)) << 7;
    int n0 = (rr0 >> 3) << 7;

    int tid = threadIdx.x;
    int lane = tid & 31, wid = tid >> 5;
    int wm = wid >> 2, wn = wid & 3;        // 2 x 4 warps
    int la = lane & 3, lg = lane >> 2;

    // cp.async write mapping (chunk-XOR swizzle)
    int gch = 2 * tid;
    int lm = gch >> 2, lc = gch & 3;
    int lsw = (lm >> 1) & 3;
    int soff0 = lm * 16 + ((lc ^ lsw) << 2);
    int soff1 = lm * 16 + (((lc + 1) ^ lsw) << 2);
    const float* gA = A + (size_t)(m0 + lm) * K + lc * 4;
    int bn = n0 + lm;
    int bok = (bn < N) ? 16 : 0;
    const float* gB = B + (size_t)(bok ? bn : 0) * K + lc * 4;
    unsigned sAb = (unsigned)__cvta_generic_to_shared(As);
    unsigned sBb = (unsigned)__cvta_generic_to_shared(Bs);

    auto issue = [&](int stage, int kb) {
        unsigned d0 = sAb + (unsigned)(stage * 2048 + soff0) * 4u;
        unsigned d1 = sAb + (unsigned)(stage * 2048 + soff1) * 4u;
        unsigned e0 = sBb + (unsigned)(stage * 2048 + soff0) * 4u;
        unsigned e1 = sBb + (unsigned)(stage * 2048 + soff1) * 4u;
        const float* pa = gA + kb;
        const float* pb = gB + kb;
        asm volatile("cp.async.cg.shared.global [%0], [%1], 16;" :: "r"(d0), "l"(pa));
        asm volatile("cp.async.cg.shared.global [%0], [%1], 16;" :: "r"(d1), "l"(pa + 4));
        asm volatile("cp.async.cg.shared.global [%0], [%1], 16, %2;" :: "r"(e0), "l"(pb), "r"(bok));
        asm volatile("cp.async.cg.shared.global [%0], [%1], 16, %2;" :: "r"(e1), "l"(pb + 4), "r"(bok));
    };

    // ldmatrix per-thread invariants.
    // A x4 per (mt, ks): mats = (q,rows 0-7),(q,rows 8-15),(q+1,rows 0-7),(q+1,rows 8-15)
    //   thread t: row = rb + (t&15), q += (t>>4)
    int l15 = lane & 15;
    int aqext = lane >> 4;                   // 0/1 -> q, q+1
    int aswz = ((l15 >> 1) & 3);             // (row>>1)&3, rb multiple of 16
    unsigned aRowOff[4];
    #pragma unroll
    for (int mt = 0; mt < 4; mt++)
        aRowOff[mt] = (unsigned)((wm * 64 + mt * 16 + l15) * 16) * 4u;
    // B x4 per (pair p, ks): mats = (q,nb..),(q+1,nb..),(q,nb+8..),(q+1,nb+8..)
    //   thread t: row = nb + (t&7) + 8*(t>>4), q += (t>>3)&1
    int brow = (lane & 7) + ((lane >> 4) << 3);
    int bqext = (lane >> 3) & 1;
    int bswz = (brow >> 1) & 3;
    unsigned bRowOff[2];
    #pragma unroll
    for (int p = 0; p < 2; p++)
        bRowOff[p] = (unsigned)((wn * 32 + p * 16 + brow) * 16) * 4u;

    float acc[4][4][4];
    #pragma unroll
    for (int i = 0; i < 4; i++)
        #pragma unroll
        for (int j = 0; j < 4; j++)
            #pragma unroll
            for (int k = 0; k < 4; k++) acc[i][j][k] = 0.f;

    int nk = K >> 4;
    issue(0, 0);  asm volatile("cp.async.commit_group;");
    issue(1, 16); asm volatile("cp.async.commit_group;");
    issue(2, 32); asm volatile("cp.async.commit_group;");

    for (int kt = 0; kt < nk; kt++) {
        asm volatile("cp.async.wait_group %0;" :: "n"(STAGES - 2));
        __syncthreads();
        int pf = kt + STAGES - 1;
        if (pf < nk) issue(pf & (STAGES - 1), pf << 4);
        asm volatile("cp.async.commit_group;");

        unsigned aStage = sAb + (unsigned)((kt & (STAGES - 1)) * 2048) * 4u;
        unsigned bStage = sBb + (unsigned)((kt & (STAGES - 1)) * 2048) * 4u;

        #pragma unroll
        for (int ks = 0; ks < 16; ks += 8) {
            int qb = ks >> 2;
            unsigned af[4][4], bf[4][2];
            #pragma unroll
            for (int mt = 0; mt < 4; mt++) {
                unsigned ad = aStage + aRowOff[mt]
                            + (unsigned)((((qb + aqext) ^ aswz) << 2) << 2);
                LDSM_X4(af[mt][0], af[mt][1], af[mt][2], af[mt][3], ad);
            }
            #pragma unroll
            for (int p = 0; p < 2; p++) {
                unsigned bd = bStage + bRowOff[p]
                            + (unsigned)((((qb + bqext) ^ bswz) << 2) << 2);
                LDSM_X4(bf[2*p][0], bf[2*p][1], bf[2*p+1][0], bf[2*p+1][1], bd);
            }
            #pragma unroll
            for (int mt = 0; mt < 4; mt++)
                #pragma unroll
                for (int nt = 0; nt < 4; nt++)
                    MMA_TF32(acc[mt][nt], af[mt][0], af[mt][1], af[mt][2], af[mt][3],
                             bf[nt][0], bf[nt][1]);
        }
    }

    // epilogue
    #pragma unroll
    for (int mt = 0; mt < 4; mt++) {
        int rbase = m0 + wm * 64 + mt * 16 + lg;
        #pragma unroll
        for (int nt = 0; nt < 4; nt++) {
            int cbase = n0 + wn * 32 + nt * 8 + la * 2;
            #pragma unroll
            for (int half = 0; half < 2; half++) {
                int rw = rbase + half * 8;
                #pragma unroll
                for (int cc = 0; cc < 2; cc++) {
                    int c = cbase + cc;
                    if (c < N) {
                        float v = acc[mt][nt][half * 2 + cc];
                        if (bias) v += bias[c];
                        if (gelu) {
                            float t = v;
                            v = to_tf32(0.5f * t * (1.0f + tanhf(0.7978845608028654f *
                                    (t + 0.044715f * t * t * t))));
                        }
                        size_t off = (size_t)rw * N + c;
                        if (res) v += res[off];
                        C[off] = v;
                    }
                }
            }
        }
    }
}

// ---------------- fused flash attention (3xTF32 mma, online softmax) -------
// 128 q-rows per block, 8 warps (16 q-rows per warp), k-tiles of 64.
#define FQ 128
#define FATT_SMEM (((FQ + 64 + 64 + FQ) * 68 + 3 * FQ) * 4)

__global__ __launch_bounds__(256)
void flash_attn(const float* __restrict__ qkv, float* __restrict__ y) {
    extern __shared__ float fsm[];
    float (*Qs)[68] = (float(*)[68])(fsm);
    float (*Ks)[68] = (float(*)[68])(fsm + FQ * 68);
    float (*Vs)[68] = (float(*)[68])(fsm + (FQ + 64) * 68);
    float (*Ps)[68] = (float(*)[68])(fsm + (FQ + 128) * 68);
    float* m_s = fsm + (2 * FQ + 128) * 68;
    float* l_s = m_s + FQ;
    float* alpha_s = l_s + FQ;

    int bh = blockIdx.y;
    int b = bh / H_, h = bh % H_;
    int q0 = blockIdx.x * FQ;
    int tid = threadIdx.x;
    int lane = tid & 31, wm = tid >> 5;
    int la = lane & 3, lg = lane >> 2;

    #pragma unroll
    for (int i = 0; i < 8; i++) {
        int f4 = tid + i * 256;
        int row = f4 >> 4, c = (f4 & 15) << 2;
        *(float4*)&Qs[row][c] =
            *(const float4*)(qkv + (size_t)(b * T_ + q0 + row) * E3_ + h * D_ + c);
    }
    if (tid < FQ) { m_s[tid] = -1e30f; l_s[tid] = 0.f; }

    float acc_o[8][4];
    #pragma unroll
    for (int i = 0; i < 8; i++)
        #pragma unroll
        for (int j = 0; j < 4; j++) acc_o[i][j] = 0.f;

    int row0 = wm * 16 + lg;
    int row1 = row0 + 8;

    int ktiles = (q0 >> 6) + 2;
    for (int kt = 0; kt < ktiles; kt++) {
        int k0 = kt << 6;
        __syncthreads();
        #pragma unroll
        for (int i = 0; i < 4; i++) {
            int f4 = tid + i * 256;
            int row = f4 >> 4, c = (f4 & 15) << 2;
            const float* base = qkv + (size_t)(b * T_ + k0 + row) * E3_ + h * D_ + c;
            *(float4*)&Ks[row][c] = *(const float4*)(base + E_);
            *(float4*)&Vs[row][c] = *(const float4*)(base + 2 * E_);
        }
        __syncthreads();

        float acc_s[8][4];
        #pragma unroll
        for (int i = 0; i < 8; i++)
            #pragma unroll
            for (int j = 0; j < 4; j++) acc_s[i][j] = 0.f;

        #pragma unroll
        for (int ks = 0; ks < 64; ks += 8) {
            unsigned ah[4], al[4];
            split_tf32(Qs[row0][ks + la    ], ah[0], al[0]);
            split_tf32(Qs[row1][ks + la    ], ah[1], al[1]);
            split_tf32(Qs[row0][ks + la + 4], ah[2], al[2]);
            split_tf32(Qs[row1][ks + la + 4], ah[3], al[3]);
            #pragma unroll
            for (int nt = 0; nt < 8; nt++) {
                int cb = nt * 8;
                unsigned bh0, bl0, bh1, bl1;
                split_tf32(Ks[cb + lg][ks + la    ], bh0, bl0);
                split_tf32(Ks[cb + lg][ks + la + 4], bh1, bl1);
                MMA_TF32(acc_s[nt], al[0], al[1], al[2], al[3], bh0, bh1);
                MMA_TF32(acc_s[nt], ah[0], ah[1], ah[2], ah[3], bl0, bl1);
                MMA_TF32(acc_s[nt], ah[0], ah[1], ah[2], ah[3], bh0, bh1);
            }
        }
        #pragma unroll
        for (int nt = 0; nt < 8; nt++) {
            int cb = nt * 8 + 2 * la;
            #pragma unroll
            for (int rr = 0; rr < 2; rr++) {
                int rloc = rr ? row1 : row0;
                int grow = q0 + rloc;
                #pragma unroll
                for (int cc = 0; cc < 2; cc++) {
                    int gcol = k0 + cb + cc;
                    float v = acc_s[nt][rr * 2 + cc] * 0.125f;
                    if (gcol > grow) v = -1e30f;
                    Ps[rloc][cb + cc] = v;
                }
            }
        }
        __syncthreads();

        {
            int r = tid >> 1, half = tid & 1;
            int c0 = half * 32;
            float mx = -1e30f;
            #pragma unroll 8
            for (int c = 0; c < 32; c++) mx = fmaxf(mx, Ps[r][c0 + c]);
            mx = fmaxf(mx, __shfl_xor_sync(0xffffffffu, mx, 1));
            float m_new = fmaxf(m_s[r], mx);
            float s = 0.f;
            #pragma unroll 8
            for (int c = 0; c < 32; c++) {
                float p = __expf(Ps[r][c0 + c] - m_new);
                Ps[r][c0 + c] = p;
                s += p;
            }
            s += __shfl_xor_sync(0xffffffffu, s, 1);
            if (half == 0) {
                float alpha = __expf(m_s[r] - m_new);
                l_s[r] = l_s[r] * alpha + s;
                m_s[r] = m_new;
                alpha_s[r] = alpha;
            }
        }
        __syncthreads();

        {
            float a0 = alpha_s[row0], a1 = alpha_s[row1];
            #pragma unroll
            for (int nt = 0; nt < 8; nt++) {
                acc_o[nt][0] *= a0; acc_o[nt][1] *= a0;
                acc_o[nt][2] *= a1; acc_o[nt][3] *= a1;
            }
        }
        #pragma unroll
        for (int ks = 0; ks < 64; ks += 8) {
            unsigned ah[4], al[4];
            split_tf32(Ps[row0][ks + la    ], ah[0], al[0]);
            split_tf32(Ps[row1][ks + la    ], ah[1], al[1]);
            split_tf32(Ps[row0][ks + la + 4], ah[2], al[2]);
            split_tf32(Ps[row1][ks + la + 4], ah[3], al[3]);
            #pragma unroll
            for (int nt = 0; nt < 8; nt++) {
                int cb = nt * 8;
                unsigned bh0, bl0, bh1, bl1;
                split_tf32(Vs[ks + la    ][cb + lg], bh0, bl0);
                split_tf32(Vs[ks + la + 4][cb + lg], bh1, bl1);
                MMA_TF32(acc_o[nt], al[0], al[1], al[2], al[3], bh0, bh1);
                MMA_TF32(acc_o[nt], ah[0], ah[1], ah[2], ah[3], bl0, bl1);
                MMA_TF32(acc_o[nt], ah[0], ah[1], ah[2], ah[3], bh0, bh1);
            }
        }
    }

    float inv0 = 1.0f / l_s[row0];
    float inv1 = 1.0f / l_s[row1];
    size_t yb0 = (size_t)(b * T_ + q0 + row0) * E_ + h * D_;
    size_t yb1 = (size_t)(b * T_ + q0 + row1) * E_ + h * D_;
    #pragma unroll
    for (int nt = 0; nt < 8; nt++) {
        int cb = nt * 8 + 2 * la;
        y[yb0 + cb    ] = to_tf32(acc_o[nt][0] * inv0);
        y[yb0 + cb + 1] = to_tf32(acc_o[nt][1] * inv0);
        y[yb1 + cb    ] = to_tf32(acc_o[nt][2] * inv1);
        y[yb1 + cb + 1] = to_tf32(acc_o[nt][3] * inv1);
    }
}

// ---------------- loss (single-pass online softmax) ------------------------
__global__ void loss_rows(const float* __restrict__ logits,
                          const int* __restrict__ targets) {
    int r = blockIdx.x;
    int b = r / (T_ - 1), t = r % (T_ - 1);
    const float* row = logits + (size_t)(b * T_ + t) * V_;
    int label = targets[b * T_ + t + 1];
    float mx = -1e30f, s = 0.f;
    for (int i = threadIdx.x; i < V_; i += 256) {
        float v = row[i];
        float mN = fmaxf(mx, v);
        s = s * __expf(mx - mN) + __expf(v - mN);
        mx = mN;
    }
    #pragma unroll
    for (int o = 16; o; o >>= 1) {
        float m2 = __shfl_down_sync(0xffffffffu, mx, o);
        float s2 = __shfl_down_sync(0xffffffffu, s, o);
        float mN = fmaxf(mx, m2);
        s = s * __expf(mx - mN) + s2 * __expf(m2 - mN);
        mx = mN;
    }
    __shared__ float smx[8], ssm[8];
    int lane = threadIdx.x & 31, wid = threadIdx.x >> 5;
    if (lane == 0) { smx[wid] = mx; ssm[wid] = s; }
    __syncthreads();
    if (threadIdx.x == 0) {
        float Mv = smx[0], Sv = ssm[0];
        #pragma unroll
        for (int i = 1; i < 8; i++) {
            float mN = fmaxf(Mv, smx[i]);
            Sv = Sv * __expf(Mv - mN) + ssm[i] * __expf(smx[i] - mN);
            Mv = mN;
        }
        g_logp[r] = row[label] - Mv - logf(Sv);
    }
}

__global__ void loss_final(float* __restrict__ out, long long pos) {
    __shared__ float red[32];
    float s = 0.f;
    for (int i = threadIdx.x; i < B_ * (T_ - 1); i += 256) s += g_logp[i];
    s = blockReduceSum(s, red);
    if (threadIdx.x == 0) out[pos] = -s / (float)(B_ * (T_ - 1));
}

// ---------------- driver ----------------------------------------------------
static inline int gemm_grid(int M, int N) {
    return (M >> 7) * ((N + 127) >> 7);
}

static inline void cvt_weights(const float* src, float* dst, long long n) {
    int n4 = (int)(n >> 2);
    cvt_tf32_kernel<<<(n4 + 255) / 256, 256>>>(
        (const float4*)src, (float4*)dst, n4);
}

extern "C" void kernel_launch(void* const* d_in, const int* in_sizes, int n_in,
                              void* d_out, int out_size) {
    const int*   idx     = (const int*)  d_in[0];
    const int*   targets = (const int*)  d_in[1];
    const float* wte     = (const float*)d_in[2];
    const float* wpe     = (const float*)d_in[3];
    const float* ln1_w   = (const float*)d_in[4];
    const float* ln1_b   = (const float*)d_in[5];
    const float* attn_w  = (const float*)d_in[6];
    const float* attn_b  = (const float*)d_in[7];
    const float* proj_w  = (const float*)d_in[8];
    const float* proj_b  = (const float*)d_in[9];
    const float* ln2_w   = (const float*)d_in[10];
    const float* ln2_b   = (const float*)d_in[11];
    const float* fc_w    = (const float*)d_in[12];
    const float* fc_b    = (const float*)d_in[13];
    const float* out_w   = (const float*)d_in[14];
    const float* out_b   = (const float*)d_in[15];
    const float* lnf_w   = (const float*)d_in[16];
    const float* lnf_b   = (const float*)d_in[17];
    float* out = (float*)d_out;

    float *x, *h, *qkv, *y, *fc;
    float *w_attn, *w_proj, *w_fc, *w_out, *w_wte;
    cudaGetSymbolAddress((void**)&x,   g_x);
    cudaGetSymbolAddress((void**)&h,   g_h);
    cudaGetSymbolAddress((void**)&qkv, g_qkv);
    cudaGetSymbolAddress((void**)&y,   g_y);
    cudaGetSymbolAddress((void**)&fc,  g_fc);
    cudaGetSymbolAddress((void**)&w_attn, g_w_attn);
    cudaGetSymbolAddress((void**)&w_proj, g_w_proj);
    cudaGetSymbolAddress((void**)&w_fc,   g_w_fc);
    cudaGetSymbolAddress((void**)&w_out,  g_w_out);
    cudaGetSymbolAddress((void**)&w_wte,  g_w_wte);

    cudaFuncSetAttribute(flash_attn,
                         cudaFuncAttributeMaxDynamicSharedMemorySize, FATT_SMEM);
    cudaFuncSetAttribute(gemm_tf32,
                         cudaFuncAttributeMaxDynamicSharedMemorySize, GEMM_SMEM);

    cvt_weights(attn_w, w_attn, (long long)L_ * E3_ * E_);
    cvt_weights(proj_w, w_proj, (long long)L_ * E_ * E_);
    cvt_weights(fc_w,   w_fc,   (long long)L_ * E4_ * E_);
    cvt_weights(out_w,  w_out,  (long long)L_ * E_ * E4_);
    cvt_weights(wte,    w_wte,  (long long)V_ * E_);

    embed_kernel<<<(M_ * E_) / 256, 256>>>(idx, wte, wpe);

    for (int l = 0; l < L_; l++) {
        ln_kernel<<<M_, 256>>>(x, ln1_w + (size_t)l * E_, ln1_b + (size_t)l * E_, h);
        gemm_tf32<<<gemm_grid(M_, E3_), 256, GEMM_SMEM>>>(
            h, w_attn + (size_t)l * E3_ * E_, attn_b + (size_t)l * E3_,
            nullptr, qkv, M_, E3_, E_, 0);
        flash_attn<<<dim3(T_ / FQ, B_ * H_), 256, FATT_SMEM>>>(qkv, y);
        gemm_tf32<<<gemm_grid(M_, E_), 256, GEMM_SMEM>>>(
            y, w_proj + (size_t)l * E_ * E_, proj_b + (size_t)l * E_,
            x, x, M_, E_, E_, 0);
        ln_kernel<<<M_, 256>>>(x, ln2_w + (size_t)l * E_, ln2_b + (size_t)l * E_, h);
        gemm_tf32<<<gemm_grid(M_, E4_), 256, GEMM_SMEM>>>(
            h, w_fc + (size_t)l * E4_ * E_, fc_b + (size_t)l * E4_,
            nullptr, fc, M_, E4_, E_, 1);
        gemm_tf32<<<gemm_grid(M_, E_), 256, GEMM_SMEM>>>(
            fc, w_out + (size_t)l * E_ * E4_, out_b + (size_t)l * E_,
            x, x, M_, E_, E4_, 0);
    }

    ln_kernel<<<M_, 256>>>(x, lnf_w, lnf_b, h);
    gemm_tf32<<<gemm_grid(M_, V_), 256, GEMM_SMEM>>>(
        h, w_wte, nullptr, nullptr, out, M_, V_, E_, 0);

    loss_rows<<<B_ * (T_ - 1), 256>>>(out, targets);
    long long pos = (long long)M_ * V_;
    if (pos < (long long)out_size)
        loss_final<<<1, 256>>>(out, pos);
}